// round 1
// baseline (speedup 1.0000x reference)
#include <cuda_runtime.h>
#include <cstdint>

// ---------------- Problem constants ----------------
#define N_ROWS   131072      // 32*16*16*16
#define DIMK     256         // E_DIM
#define NCODE    512         // N_EMBED

// Output layout (concatenated flattened outputs, float32):
// [0, 33554432)            z_q_st
// [33554432]               vq_loss
// [33554433]               commitment_loss
// [33554434, +131072)      codebook_idxs (as float)
// [33685506, +512)         hist
#define ZQ_OFF   0
#define VQ_OFF   33554432
#define CM_OFF   33554433
#define IDX_OFF  33554434
#define HIST_OFF 33685506

// ---------------- GEMM tiling ----------------
#define BM 128
#define BN 128
#define BK 32
#define TM 8
#define TN 8
#define PAD_ROW 132          // BM + 4 pad (keeps 16B alignment, reduces STS conflicts)

#define EPI_BLOCKS (N_ROWS / 8)   // 8 rows (warps) per epilogue block = 16384

// ---------------- Device scratch (no allocations allowed) ----------------
__device__ float g_ce[NCODE];        // ||e_n||^2
__device__ int   g_idx[N_ROWS];      // argmax index per row
__device__ float g_part[EPI_BLOCKS]; // per-block squared-diff partial sums

// ---------------- f32x2 packed helpers ----------------
#define FMA2(acc, a2, b2) \
    asm("fma.rn.f32x2 %0, %1, %2, %0;" : "+l"(acc) : "l"(a2), "l"(b2))
#define PACK2(d, x, y) \
    asm("mov.b64 %0, {%1, %2};" : "=l"(d) : "r"(__float_as_uint(x)), "r"(__float_as_uint(y)))
#define UNPACK2(x, y, v) \
    { unsigned int _lo, _hi; \
      asm("mov.b64 {%0, %1}, %2;" : "=r"(_lo), "=r"(_hi) : "l"(v)); \
      x = __uint_as_float(_lo); y = __uint_as_float(_hi); }

// ---------------- Kernel 0: code norms ----------------
__global__ void k_ce(const float* __restrict__ emb) {
    int n = blockIdx.x;           // 512 blocks, 64 threads
    int t = threadIdx.x;
    float4 v = *(const float4*)(emb + (size_t)n * DIMK + t * 4);
    float s = v.x * v.x + v.y * v.y + v.z * v.z + v.w * v.w;
    #pragma unroll
    for (int o = 16; o > 0; o >>= 1) s += __shfl_down_sync(0xffffffffu, s, o);
    __shared__ float ws[2];
    if ((t & 31) == 0) ws[t >> 5] = s;
    __syncthreads();
    if (t == 0) g_ce[n] = ws[0] + ws[1];
}

// ---------------- Kernel 0b: zero histogram region ----------------
__global__ void k_zero(float* __restrict__ out) {
    out[HIST_OFF + threadIdx.x] = 0.0f;   // 512 threads
}

// ---------------- Kernel 1: GEMM + argmax ----------------
// Each CTA: BM=128 rows, loops over NCODE in BN=128 chunks, K tiled by BK=32.
// sim-for-argmax(row, n) = ce[n] - 2 * dot(z_row, e_n)   (||z||^2 dropped)
__global__ __launch_bounds__(256, 2)
void k_main(const float* __restrict__ z, const float* __restrict__ emb,
            float* __restrict__ out) {
    // Shared memory layout (manually packed; red region aliases As after compute)
    //   [0,      16896)  As[BK][PAD_ROW]
    //   [16896,  33792)  Bs[BK][PAD_ROW]
    //   [33792,  35840)  ceS[NCODE]
    //   red overlaps As region: redV @0 (8KB), redI @8192 (8KB)
    __shared__ __align__(16) unsigned char sbuf[35840];
    typedef float Row[PAD_ROW];
    Row*   As  = (Row*)(sbuf);
    Row*   Bs  = (Row*)(sbuf + 16896);
    float* ceS = (float*)(sbuf + 33792);
    float* redV = (float*)(sbuf);            // [16][BM]
    int*   redI = (int*)(sbuf + 8192);       // [16][BM]

    int tid = threadIdx.x;
    int ty = tid >> 4;          // 0..15 -> row groups of 8
    int tx = tid & 15;          // 0..15 -> col groups of 8
    int rowBase = blockIdx.x * BM;

    for (int i = tid; i < NCODE; i += 256) ceS[i] = g_ce[i];

    float bestV[TM];
    int   bestI[TM];
    #pragma unroll
    for (int i = 0; i < TM; i++) { bestV[i] = -3.0e38f; bestI[i] = 0; }

    for (int nc = 0; nc < NCODE / BN; nc++) {
        unsigned long long acc[TM][TN / 2];
        #pragma unroll
        for (int i = 0; i < TM; i++)
            #pragma unroll
            for (int j = 0; j < TN / 2; j++) acc[i][j] = 0ull;

        for (int k0 = 0; k0 < DIMK; k0 += BK) {
            __syncthreads();
            // Load A tile: 128 rows x 32 cols = 1024 float4, 4 per thread
            #pragma unroll
            for (int it = 0; it < 4; it++) {
                int f  = tid + it * 256;
                int r  = f >> 3;       // 8 float4 per 32-float row
                int c4 = f & 7;
                float4 v = *(const float4*)(z + (size_t)(rowBase + r) * DIMK + k0 + c4 * 4);
                As[c4 * 4 + 0][r] = v.x;
                As[c4 * 4 + 1][r] = v.y;
                As[c4 * 4 + 2][r] = v.z;
                As[c4 * 4 + 3][r] = v.w;
            }
            // Load B tile (embedding, L2-resident)
            #pragma unroll
            for (int it = 0; it < 4; it++) {
                int f  = tid + it * 256;
                int r  = f >> 3;
                int c4 = f & 7;
                float4 v = *(const float4*)(emb + (size_t)(nc * BN + r) * DIMK + k0 + c4 * 4);
                Bs[c4 * 4 + 0][r] = v.x;
                Bs[c4 * 4 + 1][r] = v.y;
                Bs[c4 * 4 + 2][r] = v.z;
                Bs[c4 * 4 + 3][r] = v.w;
            }
            __syncthreads();

            #pragma unroll
            for (int k = 0; k < BK; k++) {
                float4 a0 = *(const float4*)&As[k][ty * TM];
                float4 a1 = *(const float4*)&As[k][ty * TM + 4];
                ulonglong2 b0 = *(const ulonglong2*)&Bs[k][tx * TN];
                ulonglong2 b1 = *(const ulonglong2*)&Bs[k][tx * TN + 4];
                unsigned long long bp[4] = {b0.x, b0.y, b1.x, b1.y};
                float av[TM] = {a0.x, a0.y, a0.z, a0.w, a1.x, a1.y, a1.z, a1.w};
                #pragma unroll
                for (int i = 0; i < TM; i++) {
                    unsigned long long ap;
                    PACK2(ap, av[i], av[i]);
                    #pragma unroll
                    for (int jp = 0; jp < TN / 2; jp++) {
                        FMA2(acc[i][jp], ap, bp[jp]);
                    }
                }
            }
        }

        // Argmax update over this column chunk (cols ascending -> first-max semantics)
        #pragma unroll
        for (int i = 0; i < TM; i++) {
            #pragma unroll
            for (int jp = 0; jp < TN / 2; jp++) {
                float d0, d1;
                UNPACK2(d0, d1, acc[i][jp]);
                int col = nc * BN + tx * TN + jp * 2;
                float v0 = ceS[col]     - 2.0f * d0;
                float v1 = ceS[col + 1] - 2.0f * d1;
                if (v0 > bestV[i]) { bestV[i] = v0; bestI[i] = col; }
                if (v1 > bestV[i]) { bestV[i] = v1; bestI[i] = col + 1; }
            }
        }
    }

    // Cross-thread reduction over the 16 tx columns per row.
    __syncthreads();   // all compute reads of As done before aliasing it with red
    #pragma unroll
    for (int i = 0; i < TM; i++) {
        redV[tx * BM + (ty * TM + i)] = bestV[i];
        redI[tx * BM + (ty * TM + i)] = bestI[i];
    }
    __syncthreads();
    if (tid < BM) {
        float bv = -3.0e38f;
        int   bi = NCODE;
        #pragma unroll 4
        for (int t = 0; t < 16; t++) {
            float v = redV[t * BM + tid];
            int   ix = redI[t * BM + tid];
            if (v > bv || (v == bv && ix < bi)) { bv = v; bi = ix; }
        }
        int row = rowBase + tid;
        g_idx[row] = bi;
        out[IDX_OFF + row] = (float)bi;
    }
}

// ---------------- Kernel 2: gather epilogue ----------------
// 8 warps per block, one row per warp. Writes z_q, histogram, loss partials.
__global__ __launch_bounds__(256)
void k_epi(const float* __restrict__ z, const float* __restrict__ emb,
           float* __restrict__ out) {
    int w = threadIdx.x >> 5;
    int l = threadIdx.x & 31;
    int row = blockIdx.x * 8 + w;
    int idx = g_idx[row];
    const float* zr = z + (size_t)row * DIMK;
    const float* er = emb + (size_t)idx * DIMK;
    float* oq = out + ZQ_OFF + (size_t)row * DIMK;

    float s = 0.0f;
    #pragma unroll
    for (int q = 0; q < 2; q++) {
        int o = q * 128 + l * 4;
        float4 e = *(const float4*)(er + o);
        float4 zz = *(const float4*)(zr + o);
        *(float4*)(oq + o) = e;
        float d0 = e.x - zz.x, d1 = e.y - zz.y, d2 = e.z - zz.z, d3 = e.w - zz.w;
        s += d0 * d0 + d1 * d1 + d2 * d2 + d3 * d3;
    }
    #pragma unroll
    for (int o = 16; o > 0; o >>= 1) s += __shfl_down_sync(0xffffffffu, s, o);

    __shared__ float ws[8];
    if (l == 0) {
        ws[w] = s;
        atomicAdd(&out[HIST_OFF + idx], 1.0f);  // exact: integer-valued float adds
    }
    __syncthreads();
    if (threadIdx.x == 0) {
        float t = 0.0f;
        #pragma unroll
        for (int i = 0; i < 8; i++) t += ws[i];   // fixed order -> deterministic
        g_part[blockIdx.x] = t;
    }
}

// ---------------- Kernel 3: finalize losses ----------------
__global__ void k_final(float* __restrict__ out) {
    __shared__ float ps[256];
    int t = threadIdx.x;
    float s = 0.0f;
    for (int i = t; i < EPI_BLOCKS; i += 256) s += g_part[i];  // fixed order
    ps[t] = s;
    __syncthreads();
    if (t == 0) {
        float tot = 0.0f;
        for (int i = 0; i < 256; i++) tot += ps[i];            // fixed order
        float vq = tot / 33554432.0f;   // N_ROWS * DIMK
        out[VQ_OFF] = vq;
        out[CM_OFF] = 0.25f * vq;       // BETA * same mean
    }
}

// ---------------- Launch ----------------
extern "C" void kernel_launch(void* const* d_in, const int* in_sizes, int n_in,
                              void* d_out, int out_size) {
    const float* z   = (const float*)d_in[0];
    const float* emb = (const float*)d_in[1];
    float* out = (float*)d_out;

    k_ce<<<NCODE, 64>>>(emb);
    k_zero<<<1, NCODE>>>(out);
    k_main<<<N_ROWS / BM, 256>>>(z, emb, out);
    k_epi<<<EPI_BLOCKS, 256>>>(z, emb, out);
    k_final<<<1, 256>>>(out);
}

// round 3
// speedup vs baseline: 2.4861x; 2.4861x over previous
#include <cuda_runtime.h>
#include <cuda_bf16.h>
#include <cstdint>

// ---------------- Problem constants ----------------
#define N_ROWS   131072      // 32*16*16*16
#define DIMK     256         // E_DIM
#define NCODE    512         // N_EMBED

// Output layout (concatenated flattened outputs, float32):
#define ZQ_OFF   0
#define VQ_OFF   33554432
#define CM_OFF   33554433
#define IDX_OFF  33554434
#define HIST_OFF 33685506

#define EPI_BLOCKS (N_ROWS / 8)   // 16384
#define MARGIN 0.8f
#define CAND   12                 // candidate list slots per row

// ---------------- Device scratch (no allocations allowed) ----------------
__device__ __align__(16) __nv_bfloat16 g_eb[NCODE * DIMK];  // bf16 embedding
__device__ float g_ce[NCODE];             // ||e_n||^2 (fp32, exact)
__device__ int   g_idx[N_ROWS];           // final argmax index per row
__device__ int   g_cnt[N_ROWS];           // candidate counts
__device__ int   g_cand[N_ROWS * CAND];   // candidate lists
__device__ float g_part[EPI_BLOCKS];      // loss partials

// ---------------- PTX helpers (all portable to compute_103) ----------------
__device__ __forceinline__ uint32_t smem_u32(const void* p) {
    uint32_t a;
    asm("{ .reg .u64 t; cvta.to.shared.u64 t, %1; cvt.u32.u64 %0, t; }" : "=r"(a) : "l"(p));
    return a;
}
#define CP_ASYNC16(dst, src) \
    asm volatile("cp.async.cg.shared.global [%0], [%1], 16;" :: "r"(dst), "l"(src) : "memory")
#define CP_COMMIT() asm volatile("cp.async.commit_group;" ::: "memory")
#define CP_WAIT0()  asm volatile("cp.async.wait_group 0;" ::: "memory")
#define LDSM4(r0, r1, r2, r3, addr) \
    asm volatile("ldmatrix.sync.aligned.m8n8.x4.shared.b16 {%0,%1,%2,%3}, [%4];" \
        : "=r"(r0), "=r"(r1), "=r"(r2), "=r"(r3) : "r"(addr))
#define MMA16816(d, a, b0, b1) \
    asm volatile("mma.sync.aligned.m16n8k16.row.col.f32.bf16.bf16.f32 " \
        "{%0,%1,%2,%3},{%4,%5,%6,%7},{%8,%9},{%0,%1,%2,%3};" \
        : "+f"((d)[0]), "+f"((d)[1]), "+f"((d)[2]), "+f"((d)[3]) \
        : "r"((a)[0]), "r"((a)[1]), "r"((a)[2]), "r"((a)[3]), "r"(b0), "r"(b1))

// Monotone float<->uint map for atomicMax on floats (any sign)
__device__ __forceinline__ unsigned fmono(float x) {
    unsigned u = __float_as_uint(x);
    return (u & 0x80000000u) ? ~u : (u | 0x80000000u);
}
__device__ __forceinline__ float funmono(unsigned u) {
    return (u & 0x80000000u) ? __uint_as_float(u ^ 0x80000000u) : __uint_as_float(~u);
}

// ---------------- SMEM layout for k_mma ----------------
// rows padded to 528B (264 bf16): conflict-free ldmatrix without swizzle
#define RS 528
#define SM_CE  0                      // 512 floats = 2048B
#define SM_RB  2048                   // 128 uints = 512B
#define SM_A   2560                   // 128 * 528 = 67584
#define SM_B0  70144                  // 128 * 528
#define SM_B1  137728                 // 128 * 528
#define SMEM_BYTES 205312

// ---------------- Kernel: prep (convert emb, norms, zero counters/hist) ----------------
__global__ void k_prep(const float* __restrict__ emb, float* __restrict__ out) {
    int n = blockIdx.x;               // 512 blocks, 64 threads
    int t = threadIdx.x;
    float4 v = *(const float4*)(emb + (size_t)n * DIMK + t * 4);
    // bf16 convert
    __nv_bfloat162 p0 = __floats2bfloat162_rn(v.x, v.y);
    __nv_bfloat162 p1 = __floats2bfloat162_rn(v.z, v.w);
    uint2 w;
    w.x = *(unsigned*)&p0;
    w.y = *(unsigned*)&p1;
    *(uint2*)((char*)g_eb + (size_t)n * 512 + t * 8) = w;
    // exact norm
    float s = v.x * v.x + v.y * v.y + v.z * v.z + v.w * v.w;
    #pragma unroll
    for (int o = 16; o > 0; o >>= 1) s += __shfl_down_sync(0xffffffffu, s, o);
    __shared__ float ws[2];
    if ((t & 31) == 0) ws[t >> 5] = s;
    __syncthreads();
    if (t == 0) g_ce[n] = ws[0] + ws[1];
    // zero candidate counters (512*64 = 32768 threads, 4 each)
    int g = n * 64 + t;
    #pragma unroll
    for (int k = 0; k < 4; k++) g_cnt[g + k * 32768] = 0;
    // zero histogram
    if (n == 0) {
        #pragma unroll
        for (int k = 0; k < 8; k++) out[HIST_OFF + t + k * 64] = 0.0f;
    }
}

// ---------------- Kernel: HMMA GEMM + margin-based candidate collection ----------------
__global__ __launch_bounds__(256, 1)
void k_mma(const float* __restrict__ z, float* __restrict__ out) {
    extern __shared__ __align__(128) unsigned char smem[];
    float*    ceS     = (float*)(smem + SM_CE);
    unsigned* rowBest = (unsigned*)(smem + SM_RB);
    uint32_t sbase = smem_u32(smem);
    uint32_t sA  = sbase + SM_A;
    uint32_t sB[2] = { sbase + SM_B0, sbase + SM_B1 };

    int tid = threadIdx.x, lane = tid & 31, wid = tid >> 5;
    int wm = wid & 3;        // M block: 32 rows
    int wn = wid >> 2;       // N block: 64 cols
    int rowBase = blockIdx.x * 128;

    for (int i = tid; i < NCODE; i += 256) ceS[i] = g_ce[i];
    if (tid < 128) rowBest[tid] = 0u;

    // ---- prefetch B chunk 0 ----
    {
        const char* src = (const char*)g_eb;
        #pragma unroll
        for (int it = 0; it < 16; it++) {
            int t = tid + it * 256;
            int r = t >> 5, c = t & 31;
            CP_ASYNC16(sB[0] + r * RS + c * 16, src + r * 512 + c * 16);
        }
        CP_COMMIT();
    }

    // ---- load + convert A tile: 128 rows x 256 fp32 -> bf16, padded rows ----
    #pragma unroll
    for (int it = 0; it < 16; it++) {
        int t = tid + it * 256;
        int r = t >> 5, c = t & 31;
        const float4* zp = (const float4*)(z + (size_t)(rowBase + r) * DIMK + c * 8);
        float4 u0 = zp[0], u1 = zp[1];
        __nv_bfloat162 p0 = __floats2bfloat162_rn(u0.x, u0.y);
        __nv_bfloat162 p1 = __floats2bfloat162_rn(u0.z, u0.w);
        __nv_bfloat162 p2 = __floats2bfloat162_rn(u1.x, u1.y);
        __nv_bfloat162 p3 = __floats2bfloat162_rn(u1.z, u1.w);
        uint4 w;
        w.x = *(unsigned*)&p0; w.y = *(unsigned*)&p1;
        w.z = *(unsigned*)&p2; w.w = *(unsigned*)&p3;
        *(uint4*)(smem + SM_A + r * RS + c * 16) = w;
    }
    CP_WAIT0();
    __syncthreads();

    // ldmatrix base addresses
    uint32_t aA0 = sA + (wm * 32 + (lane & 15)) * RS + ((lane >> 4) << 4);
    uint32_t aA1 = aA0 + 16 * RS;
    uint32_t bBofs = (uint32_t)((wn * 64 + (lane & 7) + ((lane >> 4) << 3)) * RS
                                + (((lane >> 3) & 1) << 4));

    for (int ch = 0; ch < 4; ch++) {
        // prefetch next B chunk
        if (ch < 3) {
            const char* src = (const char*)g_eb + (size_t)(ch + 1) * 128 * 512;
            uint32_t dB = sB[(ch + 1) & 1];
            #pragma unroll
            for (int it = 0; it < 16; it++) {
                int t = tid + it * 256;
                int r = t >> 5, c = t & 31;
                CP_ASYNC16(dB + r * RS + c * 16, src + r * 512 + c * 16);
            }
            CP_COMMIT();
        }

        // ---- compute chunk ch ----
        float acc[2][8][4];
        #pragma unroll
        for (int i = 0; i < 2; i++)
            #pragma unroll
            for (int j = 0; j < 8; j++)
                #pragma unroll
                for (int q = 0; q < 4; q++) acc[i][j][q] = 0.0f;

        uint32_t bB = sB[ch & 1] + bBofs;
        #pragma unroll
        for (int ks = 0; ks < 16; ks++) {
            uint32_t ko = ks * 32;
            uint32_t a[2][4];
            LDSM4(a[0][0], a[0][1], a[0][2], a[0][3], aA0 + ko);
            LDSM4(a[1][0], a[1][1], a[1][2], a[1][3], aA1 + ko);
            #pragma unroll
            for (int p = 0; p < 4; p++) {
                uint32_t b0, b1, b2, b3;
                LDSM4(b0, b1, b2, b3, bB + p * (16 * RS) + ko);
                MMA16816(acc[0][2 * p],     a[0], b0, b1);
                MMA16816(acc[0][2 * p + 1], a[0], b2, b3);
                MMA16816(acc[1][2 * p],     a[1], b0, b1);
                MMA16816(acc[1][2 * p + 1], a[1], b2, b3);
            }
        }

        int cbase = ch * 128 + wn * 64 + (lane & 3) * 2;

        // ---- pass 1: per-row running max into smem (monotone atomicMax) ----
        #pragma unroll
        for (int im = 0; im < 2; im++) {
            #pragma unroll
            for (int h = 0; h < 2; h++) {
                float m = -3.0e38f;
                #pragma unroll
                for (int jn = 0; jn < 8; jn++) {
                    float v0 = fmaf(-2.0f, acc[im][jn][h * 2],     ceS[cbase + jn * 8]);
                    float v1 = fmaf(-2.0f, acc[im][jn][h * 2 + 1], ceS[cbase + jn * 8 + 1]);
                    m = fmaxf(m, fmaxf(v0, v1));
                }
                m = fmaxf(m, __shfl_xor_sync(0xffffffffu, m, 1));
                m = fmaxf(m, __shfl_xor_sync(0xffffffffu, m, 2));
                if ((lane & 3) == 0)
                    atomicMax(&rowBest[wm * 32 + im * 16 + h * 8 + (lane >> 2)], fmono(m));
            }
        }
        __syncthreads();

        // ---- pass 2: collect candidates with v >= rowBest - MARGIN (superset-safe) ----
        #pragma unroll
        for (int im = 0; im < 2; im++) {
            #pragma unroll
            for (int h = 0; h < 2; h++) {
                int lrow = wm * 32 + im * 16 + h * 8 + (lane >> 2);
                float thr = funmono(rowBest[lrow]) - MARGIN;
                int grow = rowBase + lrow;
                #pragma unroll
                for (int jn = 0; jn < 8; jn++) {
                    #pragma unroll
                    for (int q = 0; q < 2; q++) {
                        int col = cbase + jn * 8 + q;
                        float v = fmaf(-2.0f, acc[im][jn][h * 2 + q], ceS[col]);
                        if (v >= thr) {
                            int pos = atomicAdd(&g_cnt[grow], 1);
                            if (pos < CAND) g_cand[grow * CAND + pos] = col;
                        }
                    }
                }
            }
        }

        if (ch < 3) {
            CP_WAIT0();
            __syncthreads();
        }
    }
}

// ---------------- Kernel: exact fp32 resolve (all rows) ----------------
__global__ __launch_bounds__(256) void k_rescue(const float* __restrict__ z,
                                                const float* __restrict__ emb,
                                                float* __restrict__ out) {
    int w = threadIdx.x >> 5, l = threadIdx.x & 31;
    int row = blockIdx.x * 8 + w;
    int cnt = g_cnt[row];

    if (cnt <= 1) {
        if (l == 0) {
            int bi = (cnt == 1) ? g_cand[row * CAND] : 0;
            g_idx[row] = bi;
            out[IDX_OFF + row] = (float)bi;
        }
        return;
    }

    const float4* zp = (const float4*)(z + (size_t)row * DIMK);
    float4 a = zp[l * 2], b = zp[l * 2 + 1];

    float best = -3.0e38f;
    int bi = NCODE;
    bool full = (cnt > CAND);
    int n = full ? NCODE : cnt;
    for (int ci = 0; ci < n; ci++) {
        int c = full ? ci : g_cand[row * CAND + ci];
        const float4* ep = (const float4*)(emb + (size_t)c * DIMK);
        float4 e0 = ep[l * 2], e1 = ep[l * 2 + 1];
        float s = a.x * e0.x + a.y * e0.y + a.z * e0.z + a.w * e0.w
                + b.x * e1.x + b.y * e1.y + b.z * e1.z + b.w * e1.w;
        #pragma unroll
        for (int o = 16; o > 0; o >>= 1) s += __shfl_xor_sync(0xffffffffu, s, o);
        float sim = g_ce[c] - 2.0f * s;
        if (sim > best || (sim == best && c < bi)) { best = sim; bi = c; }
    }
    if (l == 0) { g_idx[row] = bi; out[IDX_OFF + row] = (float)bi; }
}

// ---------------- Kernel: gather epilogue ----------------
__global__ __launch_bounds__(256)
void k_epi(const float* __restrict__ z, const float* __restrict__ emb,
           float* __restrict__ out) {
    int w = threadIdx.x >> 5;
    int l = threadIdx.x & 31;
    int row = blockIdx.x * 8 + w;
    int idx = g_idx[row];
    const float* zr = z + (size_t)row * DIMK;
    const float* er = emb + (size_t)idx * DIMK;
    float* oq = out + ZQ_OFF + (size_t)row * DIMK;

    float s = 0.0f;
    #pragma unroll
    for (int q = 0; q < 2; q++) {
        int o = q * 128 + l * 4;
        float4 e = *(const float4*)(er + o);
        float4 zz = *(const float4*)(zr + o);
        *(float4*)(oq + o) = e;
        float d0 = e.x - zz.x, d1 = e.y - zz.y, d2 = e.z - zz.z, d3 = e.w - zz.w;
        s += d0 * d0 + d1 * d1 + d2 * d2 + d3 * d3;
    }
    #pragma unroll
    for (int o = 16; o > 0; o >>= 1) s += __shfl_down_sync(0xffffffffu, s, o);

    __shared__ float ws[8];
    if (l == 0) {
        ws[w] = s;
        atomicAdd(&out[HIST_OFF + idx], 1.0f);  // exact: integer-valued float adds
    }
    __syncthreads();
    if (threadIdx.x == 0) {
        float t = 0.0f;
        #pragma unroll
        for (int i = 0; i < 8; i++) t += ws[i];
        g_part[blockIdx.x] = t;
    }
}

// ---------------- Kernel: finalize losses ----------------
__global__ void k_final(float* __restrict__ out) {
    __shared__ float ps[256];
    int t = threadIdx.x;
    float s = 0.0f;
    for (int i = t; i < EPI_BLOCKS; i += 256) s += g_part[i];
    ps[t] = s;
    __syncthreads();
    if (t == 0) {
        float tot = 0.0f;
        for (int i = 0; i < 256; i++) tot += ps[i];
        float vq = tot / 33554432.0f;   // N_ROWS * DIMK
        out[VQ_OFF] = vq;
        out[CM_OFF] = 0.25f * vq;
    }
}

// ---------------- Launch ----------------
extern "C" void kernel_launch(void* const* d_in, const int* in_sizes, int n_in,
                              void* d_out, int out_size) {
    const float* z   = (const float*)d_in[0];
    const float* emb = (const float*)d_in[1];
    float* out = (float*)d_out;

    cudaFuncSetAttribute(k_mma, cudaFuncAttributeMaxDynamicSharedMemorySize, SMEM_BYTES);

    k_prep<<<NCODE, 64>>>(emb, out);
    k_mma<<<N_ROWS / 128, 256, SMEM_BYTES>>>(z, out);
    k_rescue<<<EPI_BLOCKS, 256>>>(z, emb, out);
    k_epi<<<EPI_BLOCKS, 256>>>(z, emb, out);
    k_final<<<1, 256>>>(out);
}